// round 11
// baseline (speedup 1.0000x reference)
#include <cuda_runtime.h>
#include <cuda_bf16.h>
#include <cstdint>

#define NB      32
#define NRINGS  10
#define NANG    36
#define NPAIRS  (NB * NRINGS)     // 320 (batch,ring) pairs
#define NPTS    (NRINGS * NANG)   // 360
#define NTGT    16384
#define TPB     320
#define CAP     8192              // survivor capacity per (batch,ring)
#define NSAMP   512               // K1 sample count (contiguous)
#define SAMP0   7936              // K1 sample start (mid-array)

// Scratch (static device globals; no allocation).
__device__ float4       g_surv[NPAIRS * CAP];  // compacted survivors
__device__ unsigned int g_cnt[NPAIRS];          // survivor counts (zeroed by K1)
__device__ float        g_ub[NPAIRS];           // prune thresholds
__device__ float        g_part[NPAIRS];         // per-pair clamped-min sums
__device__ unsigned int g_c3;                   // K3 completion counter (self-resetting)

// Paired angles (a, 36-a): shared-cos FFMA, then +/-S*V. Constants = FFMA imms.
#define PAIR2(IA, IB, CV, SV)                        \
    { float P = fmaf(CV, U, Acc);                    \
      m[IA] = fminf(m[IA], fmaf( SV, V, P));         \
      m[IB] = fminf(m[IB], fmaf(-SV, V, P)); }

__device__ __forceinline__ void eval36(float m[NANG], float U, float V, float Acc) {
    m[ 0] = fminf(m[ 0], Acc + U);
    m[18] = fminf(m[18], Acc - U);
    m[ 9] = fminf(m[ 9], Acc + V);
    m[27] = fminf(m[27], Acc - V);
    PAIR2( 1, 35,  0.9848077530f, 0.1736481777f)
    PAIR2( 2, 34,  0.9396926208f, 0.3420201433f)
    PAIR2( 3, 33,  0.8660254038f, 0.5f)
    PAIR2( 4, 32,  0.7660444431f, 0.6427876097f)
    PAIR2( 5, 31,  0.6427876097f, 0.7660444431f)
    PAIR2( 6, 30,  0.5f,          0.8660254038f)
    PAIR2( 7, 29,  0.3420201433f, 0.9396926208f)
    PAIR2( 8, 28,  0.1736481777f, 0.9848077530f)
    PAIR2(10, 26, -0.1736481777f, 0.9848077530f)
    PAIR2(11, 25, -0.3420201433f, 0.9396926208f)
    PAIR2(12, 24, -0.5f,          0.8660254038f)
    PAIR2(13, 23, -0.6427876097f, 0.7660444431f)
    PAIR2(14, 22, -0.7660444431f, 0.6427876097f)
    PAIR2(15, 21, -0.8660254038f, 0.5f)
    PAIR2(16, 20, -0.9396926208f, 0.3420201433f)
    PAIR2(17, 19, -0.9848077530f, 0.1736481777f)
}

// ---------------- K1: sample-based per-(batch,ring) upper bound ----------------
// grid = NB blocks, 320 threads (warp = ring). Also zeroes compaction counters.
__global__ void __launch_bounds__(TPB)
k1_sample_ub(const float* __restrict__ pred, const float* __restrict__ target)
{
    const int b    = blockIdx.x;
    const int tid  = threadIdx.x;
    const int ring = tid >> 5;
    const int lane = tid & 31;

    if (tid < NRINGS) g_cnt[b * NRINGS + tid] = 0u;   // reset for K2's atomics

    const float r  = pred[b * NRINGS + ring];
    const float py = 0.15f * (float)ring - 0.7f;
    const float Kr = fmaf(r, r, fmaf(py, py, 0.0016f));
    const float INF = __int_as_float(0x7f800000);

    float m[NANG];
    #pragma unroll
    for (int a = 0; a < NANG; a++) m[a] = INF;

    const float* tg = target + ((size_t)b * NTGT + SAMP0) * 3;
    #pragma unroll 2
    for (int it = 0; it < NSAMP / 32; it++) {
        const int i = it * 32 + lane;
        float tx = tg[i * 3 + 0];
        float ty = tg[i * 3 + 1];
        float tz = tg[i * 3 + 2];
        float t2 = fmaf(tx, tx, fmaf(ty, ty, tz * tz));
        float e  = 2.0f * tx - 0.08f;
        float y  = -2.0f * ty;
        float z  = -2.0f * tz;
        float w  = fmaf(-0.08f, tx, t2);
        float Acc = fmaf(py, y, w) + Kr;
        float U   = r * e;
        float V   = r * z;
        eval36(m, U, V, Acc);
    }

    // Full butterfly per angle (all lanes get min), track max over angles.
    float ub = -INF;
    #pragma unroll
    for (int a = 0; a < NANG; a++) {
        float x = m[a];
        #pragma unroll
        for (int o = 16; o > 0; o >>= 1)
            x = fminf(x, __shfl_xor_sync(0xffffffffu, x, o));
        ub = fmaxf(ub, x);
    }
    if (lane == 0)
        g_ub[b * NRINGS + ring] = fmaf(1e-4f, fabsf(ub), ub) + 1e-4f;  // safety margin
}

// ---------------- K2: filter + compact survivors ----------------
// grid = (NTGT/256, NB), 256 threads. base = (rho-|r|)^2 + (ty-cy)^2 <= ub -> keep.
__global__ void __launch_bounds__(256)
k2_filter(const float* __restrict__ pred, const float* __restrict__ target)
{
    __shared__ float s_a[NRINGS], s_ub[NRINGS], s_Q[NRINGS];

    const int b   = blockIdx.y;
    const int tid = threadIdx.x;

    if (tid < NRINGS) {
        float a  = fabsf(pred[b * NRINGS + tid]);
        float cy = 0.15f * (float)tid - 0.7f;
        s_a[tid]  = a;
        s_Q[tid]  = fmaf(a, a, cy * cy);
        s_ub[tid] = g_ub[b * NRINGS + tid];
    }
    __syncthreads();

    const int t = blockIdx.x * 256 + tid;
    const float* tp = target + ((size_t)b * NTGT + t) * 3;
    const float tx = tp[0], ty = tp[1], tz = tp[2];

    const float ux   = tx - 0.04f;
    const float rho2 = fmaf(ux, ux, tz * tz);
    const float rho  = sqrtf(rho2);
    const float G    = fmaf(ty, ty, rho2);
    const float t2   = fmaf(tx, tx, fmaf(ty, ty, tz * tz));
    const float4 sv  = make_float4(2.0f * tx - 0.08f, -2.0f * ty, -2.0f * tz,
                                   fmaf(-0.08f, tx, t2));
    const float n2rho = -2.0f * rho;
    const float n2ty  = -2.0f * ty;

    #pragma unroll
    for (int j = 0; j < NRINGS; j++) {
        const float cy   = 0.15f * (float)j - 0.7f;
        const float base = fmaf(n2rho, s_a[j], fmaf(n2ty, cy, G + s_Q[j]));
        if (base <= s_ub[j]) {
            unsigned idx = atomicAdd(&g_cnt[b * NRINGS + j], 1u);
            if (idx < CAP)
                g_surv[(size_t)(b * NRINGS + j) * CAP + idx] = sv;
        }
    }
}

// ---------------- K3: exact eval on survivors + fused finalize ----------------
// grid = 320 blocks (one per (batch,ring)), 320 threads.
__global__ void __launch_bounds__(TPB)
k3_exact(const float* __restrict__ pred, const float* __restrict__ target,
         float* __restrict__ out)
{
    __shared__ float red[NRINGS][NANG];   // per-warp minima
    __shared__ float cl[NANG];

    const int pair = blockIdx.x;          // = b * NRINGS + ring
    const int tid  = threadIdx.x;
    const int w    = tid >> 5;
    const int lane = tid & 31;
    const int ring = pair % NRINGS;

    const float r  = pred[pair];
    const float py = 0.15f * (float)ring - 0.7f;
    const float Kr = fmaf(r, r, fmaf(py, py, 0.0016f));
    const float INF = __int_as_float(0x7f800000);

    float m[NANG];
    #pragma unroll
    for (int a = 0; a < NANG; a++) m[a] = INF;

    const unsigned n = g_cnt[pair];
    if (n <= CAP) {
        const float4* sv = g_surv + (size_t)pair * CAP;
        for (unsigned i = tid; i < n; i += TPB) {
            float4 v  = sv[i];
            float Acc = fmaf(py, v.y, v.w) + Kr;
            float U   = r * v.x;
            float V   = r * v.z;
            eval36(m, U, V, Acc);
        }
    } else {
        // Overflow fallback: full raw scan (correct; effectively never taken).
        const int b = pair / NRINGS;
        const float* tg = target + (size_t)b * NTGT * 3;
        for (int i = tid; i < NTGT; i += TPB) {
            float tx = tg[i * 3 + 0];
            float ty = tg[i * 3 + 1];
            float tz = tg[i * 3 + 2];
            float t2 = fmaf(tx, tx, fmaf(ty, ty, tz * tz));
            float Acc = fmaf(py, -2.0f * ty, fmaf(-0.08f, tx, t2)) + Kr;
            float U   = r * (2.0f * tx - 0.08f);
            float V   = r * (-2.0f * tz);
            eval36(m, U, V, Acc);
        }
    }

    // Warp butterfly per angle -> red[w][a] (static indexing only).
    #pragma unroll
    for (int a = 0; a < NANG; a++) {
        float x = m[a];
        #pragma unroll
        for (int o = 16; o > 0; o >>= 1)
            x = fminf(x, __shfl_xor_sync(0xffffffffu, x, o));
        if (lane == (a & 31)) red[w][a] = x;
    }
    __syncthreads();

    // Combine 10 warps per angle, clamp.
    if (tid < NANG) {
        float v = red[0][tid];
        #pragma unroll
        for (int ww = 1; ww < NRINGS; ww++) v = fminf(v, red[ww][tid]);
        cl[tid] = fmaxf(v, 0.0f);
    }
    __syncthreads();

    if (tid == 0) {
        float s = 0.0f;
        #pragma unroll
        for (int a = 0; a < NANG; a++) s += cl[a];   // fixed order: deterministic
        g_part[pair] = s;
        __threadfence();
        unsigned c = atomicAdd(&g_c3, 1u);
        if (c == (unsigned)(NPAIRS - 1)) {
            // Last block: deterministic serial sum of 320 partials.
            float tot = 0.0f;
            for (int i = 0; i < NPAIRS; i++) tot += g_part[i];
            out[0] = tot / (float)(NB * NPTS);
            __threadfence();
            g_c3 = 0u;                                // reset for next graph replay
        }
    }
}

extern "C" void kernel_launch(void* const* d_in, const int* in_sizes, int n_in,
                              void* d_out, int out_size) {
    const float* pred   = (const float*)d_in[0];   // (32, 10)
    const float* target = (const float*)d_in[1];   // (32, 16384, 3)
    float* out = (float*)d_out;

    k1_sample_ub<<<NB, TPB>>>(pred, target);

    dim3 g2(NTGT / 256, NB);
    k2_filter<<<g2, 256>>>(pred, target);

    k3_exact<<<NPAIRS, TPB>>>(pred, target, out);
}

// round 12
// speedup vs baseline: 2.0359x; 2.0359x over previous
#include <cuda_runtime.h>
#include <cuda_bf16.h>
#include <cstdint>

#define NB      32
#define NRINGS  10
#define NANG    36
#define NPTS    (NRINGS * NANG)     // 360
#define NTGT    16384
#define TPB     (NRINGS * 32)       // 320 threads: warp = ring
#define NBLK    444                 // 148 SMs x 3 resident -> one wave
#define NBIG    392                 // batches 0..27: 14 blocks x 37 groups
#define NG_BIG  37                  // 14*37*32 >= 16384 (dup-clamped tail)
#define NG_SML  40                  // 13*40*32 >= 16384
#define MAXT    (NG_SML * 32)       // 1280 staged targets
#define NSAMP_IT 2                  // 64-target exact sample per warp

// Monotone-encoded running max of -d2 per (batch,point). Zero = -inf sentinel;
// last block resets after the reduce so graph replays see a clean state.
__device__ unsigned int g_keys[NB * NPTS];
__device__ unsigned int g_count;

__device__ __forceinline__ unsigned int enc_f32(float f) {
    unsigned int u = __float_as_uint(f);
    return ((int)u < 0) ? ~u : (u | 0x80000000u);
}
__device__ __forceinline__ float dec_f32(unsigned int k) {
    unsigned int u = ((int)k < 0) ? (k & 0x7FFFFFFFu) : ~k;
    return __uint_as_float(u);
}

// Paired angles (a, 36-a): shared-cos FFMA, then +/-S*V. Constants = FFMA imms.
#define PAIR2(IA, IB, CV, SV)                        \
    { float P = fmaf(CV, U, Acc);                    \
      m[IA] = fminf(m[IA], fmaf( SV, V, P));         \
      m[IB] = fminf(m[IB], fmaf(-SV, V, P)); }

__device__ __forceinline__ void eval36(float m[NANG], float U, float V, float Acc) {
    m[ 0] = fminf(m[ 0], Acc + U);
    m[18] = fminf(m[18], Acc - U);
    m[ 9] = fminf(m[ 9], Acc + V);
    m[27] = fminf(m[27], Acc - V);
    PAIR2( 1, 35,  0.9848077530f, 0.1736481777f)
    PAIR2( 2, 34,  0.9396926208f, 0.3420201433f)
    PAIR2( 3, 33,  0.8660254038f, 0.5f)
    PAIR2( 4, 32,  0.7660444431f, 0.6427876097f)
    PAIR2( 5, 31,  0.6427876097f, 0.7660444431f)
    PAIR2( 6, 30,  0.5f,          0.8660254038f)
    PAIR2( 7, 29,  0.3420201433f, 0.9396926208f)
    PAIR2( 8, 28,  0.1736481777f, 0.9848077530f)
    PAIR2(10, 26, -0.1736481777f, 0.9848077530f)
    PAIR2(11, 25, -0.3420201433f, 0.9396926208f)
    PAIR2(12, 24, -0.5f,          0.8660254038f)
    PAIR2(13, 23, -0.6427876097f, 0.7660444431f)
    PAIR2(14, 22, -0.7660444431f, 0.6427876097f)
    PAIR2(15, 21, -0.8660254038f, 0.5f)
    PAIR2(16, 20, -0.9396926208f, 0.3420201433f)
    PAIR2(17, 19, -0.9848077530f, 0.1736481777f)
}

// Sample + ub + filter/compact + dense eval for one warp (ring). NG compile-time.
template<int NG>
__device__ __forceinline__ void run_warp(
    float m[NANG], const float4* __restrict__ sm,
    unsigned short* __restrict__ sidx,     // this warp's survivor-index buffer
    int lane, float r, float py, float Kr)
{
    // ---- Phase 1: exact sample on first 64 targets ----
    #pragma unroll
    for (int it = 0; it < NSAMP_IT; it++) {
        float4 v  = sm[it * 32 + lane];
        float Acc = fmaf(py, v.y, v.w) + Kr;
        float U   = r * v.x;
        float V   = r * v.z;
        eval36(m, U, V, Acc);
    }

    // ---- Phase 2: ub = max over angles of warp-min (+ margin) ----
    float ubv = -__int_as_float(0x7f800000);
    #pragma unroll
    for (int a = 0; a < NANG; a++) {
        float x = m[a];
        #pragma unroll
        for (int o = 16; o > 0; o >>= 1)
            x = fminf(x, __shfl_xor_sync(0xffffffffu, x, o));
        ubv = fmaxf(ubv, x);
    }
    const float ub = fmaf(1e-5f, fabsf(ubv), ubv) + 1e-4f;

    // ---- Phase 3: filter remaining targets, compact surviving indices ----
    // keep iff base = Acc - sqrt(U^2+V^2) <= ub  (sqrt-free form)
    unsigned cnt = 0;
    #pragma unroll 2
    for (int it = NSAMP_IT; it < NG; it++) {
        const int i = it * 32 + lane;
        float4 v  = sm[i];
        float Acc = fmaf(py, v.y, v.w) + Kr;
        float U   = r * v.x;
        float V   = r * v.z;
        float W2  = fmaf(U, U, V * V);
        float t   = Acc - ub;
        bool keep = (t <= 0.0f) || (t * t <= W2);
        unsigned mask = __ballot_sync(0xffffffffu, keep);
        if (keep) {
            unsigned pos = cnt + __popc(mask & ((1u << lane) - 1u));
            sidx[pos] = (unsigned short)i;
        }
        cnt += __popc(mask);
    }

    // ---- Phase 4: exact eval on survivors only ----
    for (unsigned k = lane; k < cnt; k += 32) {
        float4 v  = sm[sidx[k]];
        float Acc = fmaf(py, v.y, v.w) + Kr;
        float U   = r * v.x;
        float V   = r * v.z;
        eval36(m, U, V, Acc);
    }
}

__global__ void __launch_bounds__(TPB)
chamfer_fused_kernel(const float* __restrict__ pred,
                     const float* __restrict__ target,
                     float* __restrict__ out)
{
    __shared__ float4 sm[MAXT];                       // 20 KB
    __shared__ unsigned short sidx[NRINGS][MAXT];     // 25.6 KB survivor indices
    __shared__ float  wsum[NRINGS];
    __shared__ unsigned int is_last;

    const int bid = blockIdx.x;
    const int tid = threadIdx.x;

    // Block -> (batch, tile). Batches 0..27: 14 tiles of 37 groups; 28..31: 13 of 40.
    int batch, wb, ng;
    if (bid < NBIG) { batch = bid / 14;            wb = bid - batch * 14;  ng = NG_BIG; }
    else            { int e = bid - NBIG; int q = e / 13;
                      batch = 28 + q;              wb = e - q * 13;        ng = NG_SML; }

    const int start = wb * ng * 32;
    const int n     = ng * 32;

    // Stage + preprocess (clamped tail): (2tx-0.08, -2ty, -2tz, t2-0.08tx)
    const float* tg = target + (size_t)batch * NTGT * 3;
    for (int i = tid; i < n; i += TPB) {
        int gi = min(start + i, NTGT - 1);
        float tx = tg[gi * 3 + 0];
        float ty = tg[gi * 3 + 1];
        float tz = tg[gi * 3 + 2];
        float t2 = tx * tx + ty * ty + tz * tz;
        sm[i] = make_float4(2.0f * tx - 0.08f, -2.0f * ty, -2.0f * tz,
                            fmaf(-0.08f, tx, t2));
    }
    __syncthreads();

    const int ring = tid >> 5;
    const int lane = tid & 31;

    const float r  = pred[batch * NRINGS + ring];
    const float py = 0.15f * (float)ring - 0.7f;
    const float Kr = fmaf(r, r, fmaf(py, py, 0.0016f));
    const unsigned int pbase = (unsigned)(batch * NPTS + ring * NANG);
    const float INF = __int_as_float(0x7f800000);

    float m[NANG];
    #pragma unroll
    for (int a = 0; a < NANG; a++) m[a] = INF;

    if (ng == NG_BIG) run_warp<NG_BIG>(m, sm, sidx[ring], lane, r, py, Kr);
    else              run_warp<NG_SML>(m, sm, sidx[ring], lane, r, py, Kr);

    // Final fold: butterfly min per angle, REDG.MAX into g_keys.
    #pragma unroll
    for (int a = 0; a < NANG; a++) {
        float x = m[a];
        #pragma unroll
        for (int o = 16; o > 0; o >>= 1)
            x = fminf(x, __shfl_xor_sync(0xffffffffu, x, o));
        if (lane == (a & 31))
            atomicMax(&g_keys[pbase + a], enc_f32(-x));
    }

    // ---- last-block finalize (fused) ----
    __threadfence();
    if (tid == 0)
        is_last = (atomicAdd(&g_count, 1u) == (unsigned)(NBLK - 1));
    __syncthreads();
    if (!is_last) return;
    __threadfence();

    uint4* keys4 = (uint4*)g_keys;
    const int n4 = (NB * NPTS) / 4;     // 2880
    float s = 0.0f;
    for (int i = tid; i < n4; i += TPB) {
        uint4 k = keys4[i];
        s += fmaxf(-dec_f32(k.x), 0.0f);
        s += fmaxf(-dec_f32(k.y), 0.0f);
        s += fmaxf(-dec_f32(k.z), 0.0f);
        s += fmaxf(-dec_f32(k.w), 0.0f);
    }
    #pragma unroll
    for (int o = 16; o > 0; o >>= 1) s += __shfl_down_sync(0xffffffffu, s, o);
    if (lane == 0) wsum[ring] = s;
    __syncthreads();
    if (tid == 0) {
        float tot = 0.0f;
        #pragma unroll
        for (int w = 0; w < NRINGS; w++) tot += wsum[w];
        out[0] = tot / (float)(NB * NPTS);
    }
    __syncthreads();   // all g_keys reads complete before reset

    const uint4 z4 = make_uint4(0u, 0u, 0u, 0u);
    for (int i = tid; i < n4; i += TPB) keys4[i] = z4;
    if (tid == 0) g_count = 0u;
}

extern "C" void kernel_launch(void* const* d_in, const int* in_sizes, int n_in,
                              void* d_out, int out_size) {
    const float* pred   = (const float*)d_in[0];   // (32, 10)
    const float* target = (const float*)d_in[1];   // (32, 16384, 3)
    float* out = (float*)d_out;

    chamfer_fused_kernel<<<NBLK, TPB>>>(pred, target, out);
}